// round 14
// baseline (speedup 1.0000x reference)
#include <cuda_runtime.h>
#include <cuda_fp16.h>
#include <cstdint>

#define N_PAD   50048
#define DIM     256
#define NEG     0.2f
#define LN_EPS  1e-5f
#define THREADS 512

// SMEM: B 4 chunk-planes | A16 4 planes | reduction buffers
#define B_CHUNK  32768
#define A16_OFF  131072
#define BUF_OFF  163840
#define SMEM_BYTES (BUF_OFF + 2432 * 4)   // 173568

// ---------------- scratch ----------------
__device__ unsigned char g_mask[3 * N_PAD];
__device__ uint32_t g_wh[4 * 256 * 32];   // Wr fp16 chunk-major pairs

// ---------------- helpers ----------------
__device__ __forceinline__ uint32_t pack_f16(float a, float b) {
    __half2 h = __floats2half2_rn(a, b);
    return *reinterpret_cast<uint32_t*>(&h);
}
__device__ __forceinline__ uint32_t s2u(const void* p) {
    return (uint32_t)__cvta_generic_to_shared(p);
}
__device__ __forceinline__ uint32_t swz(uint32_t off) {
    return off ^ ((off >> 3) & 0x70);
}
__device__ __forceinline__ void cpasync16(uint32_t dst, const void* src) {
    asm volatile("cp.async.cg.shared.global [%0], [%1], 16;" :: "r"(dst), "l"(src));
}
__device__ __forceinline__ void cpcommit() { asm volatile("cp.async.commit_group;"); }
__device__ __forceinline__ void cpwait0()  { asm volatile("cp.async.wait_group 0;"); }
__device__ __forceinline__ void ldmx4(uint32_t r[4], uint32_t addr) {
    asm volatile("ldmatrix.sync.aligned.m8n8.x4.shared.b16 {%0,%1,%2,%3}, [%4];"
                 : "=r"(r[0]), "=r"(r[1]), "=r"(r[2]), "=r"(r[3]) : "r"(addr));
}
__device__ __forceinline__ void mma16816(float c[4], const uint32_t a[4],
                                         uint32_t b0, uint32_t b1) {
    asm("mma.sync.aligned.m16n8k16.row.col.f32.f16.f16.f32 "
        "{%0,%1,%2,%3}, {%4,%5,%6,%7}, {%8,%9}, {%0,%1,%2,%3};"
        : "+f"(c[0]), "+f"(c[1]), "+f"(c[2]), "+f"(c[3])
        : "r"(a[0]), "r"(a[1]), "r"(a[2]), "r"(a[3]), "r"(b0), "r"(b1));
}
__device__ __forceinline__ float head_w(float q, float kv, float n1) {
    float x1 = q + kv;
    float z1 = fmaxf(x1, NEG * x1);
    float z0 = fmaxf(q,  NEG * q);
    float m  = fmaxf(z1, z0);
    float e1 = expf(z1 - m);
    float e0 = expf(z0 - m);
    float f1 = n1 * e1;
    return f1 / (f1 + (4.0f - n1) * e0);
}

// ---------------- prep (validated R7/R8) ----------------
#define W_BLOCKS 16
__global__ void prep_kernel(const float* __restrict__ Wr,
                            const int* __restrict__ d0,
                            const int* __restrict__ d1,
                            const int* __restrict__ d2, int E4)
{
    int b = blockIdx.x;
    if (b < W_BLOCKS) {
        int t   = b * 256 + threadIdx.x;
        int nc  = t >> 4;
        int seg = t & 15;
        int kb  = seg * 16;
        uint32_t h[8];
        #pragma unroll
        for (int p = 0; p < 8; p++) {
            float x0 = Wr[(size_t)(kb + 2 * p)     * 256 + nc];
            float x1 = Wr[(size_t)(kb + 2 * p + 1) * 256 + nc];
            h[p] = pack_f16(x0, x1);
        }
        int c = seg >> 2;
        size_t base = ((size_t)(c * 256 + nc)) * 32 + (seg & 3) * 8;
        *(uint4*)&g_wh[base]     = make_uint4(h[0], h[1], h[2], h[3]);
        *(uint4*)&g_wh[base + 4] = make_uint4(h[4], h[5], h[6], h[7]);
        return;
    }
    b -= W_BLOCKS;
    int i = b * 256 + threadIdx.x;
    if (i >= E4) return;
    int4 a  = ((const int4*)d0)[i];
    int4 bb = ((const int4*)d1)[i];
    int4 cc = ((const int4*)d2)[i];
    if (!g_mask[a.x]) g_mask[a.x] = 1;
    if (!g_mask[a.y]) g_mask[a.y] = 1;
    if (!g_mask[a.z]) g_mask[a.z] = 1;
    if (!g_mask[a.w]) g_mask[a.w] = 1;
    if (!g_mask[N_PAD + bb.x]) g_mask[N_PAD + bb.x] = 1;
    if (!g_mask[N_PAD + bb.y]) g_mask[N_PAD + bb.y] = 1;
    if (!g_mask[N_PAD + bb.z]) g_mask[N_PAD + bb.z] = 1;
    if (!g_mask[N_PAD + bb.w]) g_mask[N_PAD + bb.w] = 1;
    if (!g_mask[2 * N_PAD + cc.x]) g_mask[2 * N_PAD + cc.x] = 1;
    if (!g_mask[2 * N_PAD + cc.y]) g_mask[2 * N_PAD + cc.y] = 1;
    if (!g_mask[2 * N_PAD + cc.z]) g_mask[2 * N_PAD + cc.z] = 1;
    if (!g_mask[2 * N_PAD + cc.w]) g_mask[2 * N_PAD + cc.w] = 1;
}

// ---------------- persistent GEMM + register epilogue ----------------
__global__ __launch_bounds__(THREADS, 1)
void gemm_epilogue(const float* __restrict__ feat,
                   const float* __restrict__ br,
                   const float* __restrict__ rel_q,
                   const float* __restrict__ rel_k,
                   const float* __restrict__ ln_g,
                   const float* __restrict__ ln_b,
                   float* __restrict__ out, int n)
{
    extern __shared__ char smem[];
    const uint32_t su = s2u(smem);
    const int tid  = threadIdx.x;
    const int wid  = tid >> 5;
    const int lane = tid & 31;
    const int wm   = wid & 1;      // rows wm*32..+31
    const int wn   = wid >> 1;     // cols wn*32..+31

    // reduction buffers
    float* pqb = (float*)(smem + BUF_OFF);       // [64][4][2]
    float* pkb = pqb + 512;                      // [64][4][2]
    float* s1b = pkb + 512;                      // [64][8]
    float* s2b = s1b + 512;                      // [64][8]
    float* wb  = s2b + 512;                      // [64][4]
    float* mub = wb + 256;                       // [64]
    float* rsb = mub + 64;                       // [64]

    // ---- load ALL of B once (4 chunks, 128 KB) ----
    {
        const int bn = tid >> 1;
        const int bj = (tid & 1) * 4;
        #pragma unroll
        for (int c = 0; c < 4; c++) {
            const uint32_t* bf = g_wh + (size_t)c * 8192 + (size_t)bn * 32 + bj * 4;
            const uint32_t dstb = su + (uint32_t)c * B_CHUNK;
            #pragma unroll
            for (int u = 0; u < 4; u++)
                cpasync16(dstb + swz((uint32_t)(bn * 128 + (bj + u) * 16)), bf + u * 4);
        }
        cpcommit();
    }

    // per-thread column constants (cols = wn*32 + nt*8 + cq + u)
    const int cq = (lane & 3) * 2;
    const int rg = lane >> 2;
    float rqv[4][2], rkv[4][2], brv[4][2];
    #pragma unroll
    for (int nt = 0; nt < 4; nt++)
        #pragma unroll
        for (int u = 0; u < 2; u++) {
            int col = wn * 32 + nt * 8 + cq + u;
            rqv[nt][u] = rel_q[col];
            rkv[nt][u] = rel_k[col];
            brv[nt][u] = br[col];
        }

    // fragment address components (validated R12/R13)
    const int l7  = lane & 7;
    const int q01 = (lane >> 3) & 1;
    const int q23 = lane >> 4;
    uint32_t arowb[2];
    #pragma unroll
    for (int mt = 0; mt < 2; mt++)
        arowb[mt] = (uint32_t)((wm * 32 + mt * 16 + q01 * 8 + l7) * 128);
    const uint32_t bg   = (uint32_t)((lane >> 3) * 16);
    const uint32_t brb0 = (uint32_t)((wn * 32 + l7) * 128);

    // A staging mapping (validated R13)
    const int arow = tid >> 3;
    const int aseg = tid & 7;
    char* aplane = smem + A16_OFF + (aseg >> 1) * 8192;
    const uint32_t abase = (uint32_t)(arow * 128 + (aseg & 1) * 64);
    const int hh = wn >> 1;   // head of this warp's columns

    const int ntiles = (n + 63) >> 6;
    const int stride = gridDim.x;

    // ---- prologue: A(first) load + convert ----
    {
        int s0 = blockIdx.x;
        int gr = s0 * 64 + arow; if (gr >= n) gr = n - 1;
        const float4* af = (const float4*)(feat + (size_t)gr * 256 + aseg * 32);
        float4 v[8];
        #pragma unroll
        for (int i = 0; i < 8; i++) v[i] = af[i];
        #pragma unroll
        for (int j = 0; j < 4; j++) {
            uint4 h = make_uint4(pack_f16(v[2*j].x,   v[2*j].y),
                                 pack_f16(v[2*j].z,   v[2*j].w),
                                 pack_f16(v[2*j+1].x, v[2*j+1].y),
                                 pack_f16(v[2*j+1].z, v[2*j+1].w));
            *(uint4*)(aplane + swz(abase + j * 16)) = h;
        }
    }
    cpwait0();   // B resident

    for (int s = blockIdx.x; s < ntiles; s += stride) {
        const int row0 = s * 64;
        __syncthreads();   // B1: A16(s) ready (and B on first iter)

        // ---- compute: identical to R13 ----
        float acc[2][4][4];
        #pragma unroll
        for (int mt = 0; mt < 2; mt++)
            #pragma unroll
            for (int nt = 0; nt < 4; nt++)
                #pragma unroll
                for (int q = 0; q < 4; q++) acc[mt][nt][q] = 0.0f;

        #pragma unroll
        for (int c = 0; c < 4; c++) {
            const uint32_t sa = su + A16_OFF + (uint32_t)c * 8192;
            const uint32_t sb = su + (uint32_t)c * B_CHUNK;
            #pragma unroll
            for (int p = 0; p < 2; p++) {
                uint32_t bh[4][4];
                #pragma unroll
                for (int nt = 0; nt < 4; nt++)
                    ldmx4(bh[nt], sb + swz(brb0 + (uint32_t)(nt * 1024 + p * 64) + bg));
                #pragma unroll
                for (int kk = 0; kk < 2; kk++) {
                    uint32_t ah[2][4];
                    #pragma unroll
                    for (int mt = 0; mt < 2; mt++)
                        ldmx4(ah[mt], sa + swz(arowb[mt] + (uint32_t)((p * 2 + kk) * 32 + q23 * 16)));
                    mma16816(acc[0][0], ah[0], bh[0][2*kk], bh[0][2*kk+1]);
                    mma16816(acc[1][0], ah[1], bh[0][2*kk], bh[0][2*kk+1]);
                    mma16816(acc[0][1], ah[0], bh[1][2*kk], bh[1][2*kk+1]);
                    mma16816(acc[1][1], ah[1], bh[1][2*kk], bh[1][2*kk+1]);
                    mma16816(acc[0][2], ah[0], bh[2][2*kk], bh[2][2*kk+1]);
                    mma16816(acc[1][2], ah[1], bh[2][2*kk], bh[2][2*kk+1]);
                    mma16816(acc[0][3], ah[0], bh[3][2*kk], bh[3][2*kk+1]);
                    mma16816(acc[1][3], ah[1], bh[3][2*kk], bh[3][2*kk+1]);
                }
            }
        }

        // ---- issue A(next) LDGs now; consumed after phase2 (latency hidden) ----
        const int snext = s + stride;
        float4 vA[8];
        if (snext < ntiles) {
            int gr = snext * 64 + arow; if (gr >= n) gr = n - 1;
            const float4* af = (const float4*)(feat + (size_t)gr * 256 + aseg * 32);
            #pragma unroll
            for (int i = 0; i < 8; i++) vA[i] = af[i];
        }

        // ---- phase 1: v = acc + br; per-head partial dots; quad-reduce ----
        float pq[2][2] = {{0,0},{0,0}}, pk[2][2] = {{0,0},{0,0}};
        #pragma unroll
        for (int mt = 0; mt < 2; mt++)
            #pragma unroll
            for (int nt = 0; nt < 4; nt++) {
                float v0 = acc[mt][nt][0] + brv[nt][0];
                float v1 = acc[mt][nt][1] + brv[nt][1];
                float v2 = acc[mt][nt][2] + brv[nt][0];
                float v3 = acc[mt][nt][3] + brv[nt][1];
                acc[mt][nt][0] = v0; acc[mt][nt][1] = v1;
                acc[mt][nt][2] = v2; acc[mt][nt][3] = v3;
                pq[mt][0] = fmaf(v0, rqv[nt][0], fmaf(v1, rqv[nt][1], pq[mt][0]));
                pq[mt][1] = fmaf(v2, rqv[nt][0], fmaf(v3, rqv[nt][1], pq[mt][1]));
                pk[mt][0] = fmaf(v0, rkv[nt][0], fmaf(v1, rkv[nt][1], pk[mt][0]));
                pk[mt][1] = fmaf(v2, rkv[nt][0], fmaf(v3, rkv[nt][1], pk[mt][1]));
            }
        #pragma unroll
        for (int o = 1; o <= 2; o <<= 1) {
            #pragma unroll
            for (int mt = 0; mt < 2; mt++)
                #pragma unroll
                for (int hf = 0; hf < 2; hf++) {
                    pq[mt][hf] += __shfl_xor_sync(0xffffffffu, pq[mt][hf], o);
                    pk[mt][hf] += __shfl_xor_sync(0xffffffffu, pk[mt][hf], o);
                }
        }
        if ((lane & 3) == 0) {
            #pragma unroll
            for (int mt = 0; mt < 2; mt++)
                #pragma unroll
                for (int hf = 0; hf < 2; hf++) {
                    int rl = wm * 32 + mt * 16 + rg + hf * 8;
                    pqb[(rl * 4 + hh) * 2 + (wn & 1)] = pq[mt][hf];
                    pkb[(rl * 4 + hh) * 2 + (wn & 1)] = pk[mt][hf];
                }
        }
        __syncthreads();   // B2

        // ---- phase 2: w per (row, head) ----
        if (tid < 256) {
            int r = tid >> 2, h = tid & 3;
            float q  = pqb[(r * 4 + h) * 2] + pqb[(r * 4 + h) * 2 + 1];
            float kv = pkb[(r * 4 + h) * 2] + pkb[(r * 4 + h) * 2 + 1];
            int grow = row0 + r;
            float n1 = 1.0f + (float)g_mask[grow] + (float)g_mask[N_PAD + grow]
                            + (float)g_mask[2 * N_PAD + grow];
            wb[r * 4 + h] = head_w(q, kv, n1);
        }
        __syncthreads();   // B3

        // ---- convert prefetched A (LDG results needed here; ~long window elapsed) ----
        uint32_t hA[16];
        if (snext < ntiles) {
            #pragma unroll
            for (int j = 0; j < 8; j++) {
                hA[2*j]   = pack_f16(vA[j].x, vA[j].y);
                hA[2*j+1] = pack_f16(vA[j].z, vA[j].w);
            }
        }

        // ---- phase 3: o = relu(v*w); LN partial sums; quad-reduce ----
        float s1[2][2] = {{0,0},{0,0}}, s2[2][2] = {{0,0},{0,0}};
        #pragma unroll
        for (int mt = 0; mt < 2; mt++) {
            int rl0 = wm * 32 + mt * 16 + rg;
            float w0 = wb[rl0 * 4 + hh];
            float w1 = wb[(rl0 + 8) * 4 + hh];
            #pragma unroll
            for (int nt = 0; nt < 4; nt++) {
                float o0 = fmaxf(acc[mt][nt][0] * w0, 0.f);
                float o1 = fmaxf(acc[mt][nt][1] * w0, 0.f);
                float o2 = fmaxf(acc[mt][nt][2] * w1, 0.f);
                float o3 = fmaxf(acc[mt][nt][3] * w1, 0.f);
                acc[mt][nt][0] = o0; acc[mt][nt][1] = o1;
                acc[mt][nt][2] = o2; acc[mt][nt][3] = o3;
                s1[mt][0] += o0 + o1;
                s1[mt][1] += o2 + o3;
                s2[mt][0] = fmaf(o0, o0, fmaf(o1, o1, s2[mt][0]));
                s2[mt][1] = fmaf(o2, o2, fmaf(o3, o3, s2[mt][1]));
            }
        }
        #pragma unroll
        for (int o = 1; o <= 2; o <<= 1) {
            #pragma unroll
            for (int mt = 0; mt < 2; mt++)
                #pragma unroll
                for (int hf = 0; hf < 2; hf++) {
                    s1[mt][hf] += __shfl_xor_sync(0xffffffffu, s1[mt][hf], o);
                    s2[mt][hf] += __shfl_xor_sync(0xffffffffu, s2[mt][hf], o);
                }
        }
        if ((lane & 3) == 0) {
            #pragma unroll
            for (int mt = 0; mt < 2; mt++)
                #pragma unroll
                for (int hf = 0; hf < 2; hf++) {
                    int rl = wm * 32 + mt * 16 + rg + hf * 8;
                    s1b[rl * 8 + wn] = s1[mt][hf];
                    s2b[rl * 8 + wn] = s2[mt][hf];
                }
        }
        __syncthreads();   // B4

        // ---- phase 4: mu / rsqrt per row ----
        if (tid < 64) {
            float a = 0.f, b2 = 0.f;
            #pragma unroll
            for (int w = 0; w < 8; w++) { a += s1b[tid * 8 + w]; b2 += s2b[tid * 8 + w]; }
            float mu  = a * (1.0f / 256.0f);
            float var = b2 * (1.0f / 256.0f) - mu * mu;
            mub[tid] = mu;
            rsb[tid] = rsqrtf(var + LN_EPS);
        }
        __syncthreads();   // B5

        // ---- phase 5: normalize + store ----
        #pragma unroll
        for (int mt = 0; mt < 2; mt++)
            #pragma unroll
            for (int hf = 0; hf < 2; hf++) {
                int rl = wm * 32 + mt * 16 + rg + hf * 8;
                int grow = row0 + rl;
                if (grow >= n) continue;
                float mu = mub[rl];
                float rs = rsb[rl];
                #pragma unroll
                for (int nt = 0; nt < 4; nt++) {
                    int col = wn * 32 + nt * 8 + cq;
                    float g0 = __ldg(&ln_g[col]),     g1 = __ldg(&ln_g[col + 1]);
                    float b0 = __ldg(&ln_b[col]),     b1 = __ldg(&ln_b[col + 1]);
                    float o0 = acc[mt][nt][hf * 2];
                    float o1 = acc[mt][nt][hf * 2 + 1];
                    float2 st;
                    st.x = (o0 - mu) * rs * g0 + b0;
                    st.y = (o1 - mu) * rs * g1 + b1;
                    *(float2*)&out[(size_t)grow * 256 + col] = st;
                }
            }

        // ---- stage A(next) to A16 (all warps past B2 => LDSM(s) complete) ----
        if (snext < ntiles) {
            #pragma unroll
            for (int j = 0; j < 4; j++) {
                uint4 h = make_uint4(hA[4*j], hA[4*j+1], hA[4*j+2], hA[4*j+3]);
                *(uint4*)(aplane + swz(abase + j * 16)) = h;
            }
        }
    }
}

// ---------------- launcher ----------------
extern "C" void kernel_launch(void* const* d_in, const int* in_sizes, int n_in,
                              void* d_out, int out_size)
{
    const float* feat  = (const float*)d_in[0];
    const float* Wr    = (const float*)d_in[3];
    const float* br    = (const float*)d_in[4];
    const float* rel_q = (const float*)d_in[7];
    const float* rel_k = (const float*)d_in[8];
    const float* ln_g  = (const float*)d_in[9];
    const float* ln_b  = (const float*)d_in[10];
    const int*   dst0  = (const int*)d_in[12];
    const int*   dst1  = (const int*)d_in[14];
    const int*   dst2  = (const int*)d_in[16];

    int n  = in_sizes[0] / DIM;   // 50000
    int E  = in_sizes[12];        // 400000
    int E4 = E / 4;

    static bool attr_set = false;
    if (!attr_set) {
        cudaFuncSetAttribute(gemm_epilogue,
                             cudaFuncAttributeMaxDynamicSharedMemorySize, SMEM_BYTES);
        cudaFuncSetAttribute(gemm_epilogue,
                             cudaFuncAttributePreferredSharedMemoryCarveout, 100);
        attr_set = true;
    }

    int scatter_blocks = (E4 + 255) / 256;
    prep_kernel<<<W_BLOCKS + scatter_blocks, 256>>>(Wr, dst0, dst1, dst2, E4);

    gemm_epilogue<<<148, THREADS, SMEM_BYTES>>>(
        feat, br, rel_q, rel_k, ln_g, ln_b, (float*)d_out, n);
}